// round 7
// baseline (speedup 1.0000x reference)
#include <cuda_runtime.h>
#include <cstdint>

using u64 = unsigned long long;
using u32 = unsigned int;

// Problem constants
constexpr int B = 32;
constexpr int N = 131072;
constexpr int K = 1024;

// Config
constexpr int T     = 1024;     // threads per CTA (one CTA per batch)
constexpr int CH    = 256;      // points per chunk
constexpr int NCH   = N / CH;   // 512 chunks per batch
constexpr int CELLS = 4096;     // 16^3 Morton cells per batch

// Static device scratch (allocation-free)
__device__ __align__(16) float4 g_p[B * N];     // sorted AoS: x,y,z,origidx
__device__ __align__(16) float  g_dist[B * N];  // per-point min dist
__device__ int   g_hist[B * CELLS];
__device__ int   g_cur[B * CELLS];
__device__ float g_bbox[B * NCH * 6];

// ---- Morton cell id (4 bits/dim) ----
__device__ __forceinline__ u32 expand3_4(u32 v) {
    return (v & 1u) | ((v & 2u) << 2) | ((v & 4u) << 4) | ((v & 8u) << 6);
}
__device__ __forceinline__ int cell_of(float x, float y, float z) {
    int ix = min(15, max(0, (int)((x + 4.5f) * (16.0f / 9.0f))));
    int iy = min(15, max(0, (int)((y + 4.5f) * (16.0f / 9.0f))));
    int iz = min(15, max(0, (int)((z + 4.5f) * (16.0f / 9.0f))));
    return (int)(expand3_4((u32)ix) | (expand3_4((u32)iy) << 1) |
                 (expand3_4((u32)iz) << 2));
}

// ---- Preprocessing ----
__global__ void zero_hist_kernel() {
    int i = blockIdx.x * blockDim.x + threadIdx.x;
    if (i < B * CELLS) g_hist[i] = 0;
}

__global__ void cell_hist_kernel(const float* __restrict__ pts) {
    int i = blockIdx.x * blockDim.x + threadIdx.x;
    if (i >= B * N) return;
    float x = pts[3 * i], y = pts[3 * i + 1], z = pts[3 * i + 2];
    int c = cell_of(x, y, z);
    atomicAdd(&g_hist[(i / N) * CELLS + c], 1);
}

__global__ void cell_scan_kernel() {   // exclusive scan, one CTA per batch
    __shared__ int wt[32];
    int b = blockIdx.x, t = threadIdx.x;
    int lane = t & 31, w = t >> 5;
    int v[4], s = 0;
    #pragma unroll
    for (int j = 0; j < 4; j++) { v[j] = g_hist[b * CELLS + t * 4 + j]; s += v[j]; }
    int ps = s;
    #pragma unroll
    for (int o = 1; o < 32; o <<= 1) {
        int u = __shfl_up_sync(0xffffffffu, ps, o);
        if (lane >= o) ps += u;
    }
    if (lane == 31) wt[w] = ps;
    __syncthreads();
    if (w == 0) {
        int x = wt[lane];
        #pragma unroll
        for (int o = 1; o < 32; o <<= 1) {
            int u = __shfl_up_sync(0xffffffffu, x, o);
            if (lane >= o) x += u;
        }
        wt[lane] = x;
    }
    __syncthreads();
    int run = (w > 0 ? wt[w - 1] : 0) + (ps - s);
    #pragma unroll
    for (int j = 0; j < 4; j++) { g_cur[b * CELLS + t * 4 + j] = run; run += v[j]; }
}

__global__ void scatter_kernel(const float* __restrict__ pts) {
    int i = blockIdx.x * blockDim.x + threadIdx.x;
    if (i >= B * N) return;
    int b = i / N, j = i - b * N;
    float x = pts[3 * i], y = pts[3 * i + 1], z = pts[3 * i + 2];
    int c = cell_of(x, y, z);
    int pos = atomicAdd(&g_cur[b * CELLS + c], 1);
    int o = b * N + pos;
    g_p[o] = make_float4(x, y, z, __int_as_float(j));  // one STG.128
    g_dist[o] = 1e10f;
}

__global__ void chunk_bbox_kernel() {   // one 256-thread block per chunk
    __shared__ float rmn[3][8], rmx[3][8];
    int ch = blockIdx.x, t = threadIdx.x;
    int lane = t & 31, w = t >> 5;
    float4 p = g_p[ch * CH + t];
    float mnx = p.x, mxx = p.x, mny = p.y, mxy = p.y, mnz = p.z, mxz = p.z;
    #pragma unroll
    for (int s = 16; s > 0; s >>= 1) {
        mnx = fminf(mnx, __shfl_xor_sync(0xffffffffu, mnx, s));
        mxx = fmaxf(mxx, __shfl_xor_sync(0xffffffffu, mxx, s));
        mny = fminf(mny, __shfl_xor_sync(0xffffffffu, mny, s));
        mxy = fmaxf(mxy, __shfl_xor_sync(0xffffffffu, mxy, s));
        mnz = fminf(mnz, __shfl_xor_sync(0xffffffffu, mnz, s));
        mxz = fmaxf(mxz, __shfl_xor_sync(0xffffffffu, mxz, s));
    }
    if (lane == 0) {
        rmn[0][w] = mnx; rmx[0][w] = mxx;
        rmn[1][w] = mny; rmx[1][w] = mxy;
        rmn[2][w] = mnz; rmx[2][w] = mxz;
    }
    __syncthreads();
    if (t == 0) {
        float a0 = rmn[0][0], b0 = rmx[0][0];
        float a1 = rmn[1][0], b1 = rmx[1][0];
        float a2 = rmn[2][0], b2 = rmx[2][0];
        #pragma unroll
        for (int i = 1; i < 8; i++) {
            a0 = fminf(a0, rmn[0][i]); b0 = fmaxf(b0, rmx[0][i]);
            a1 = fminf(a1, rmn[1][i]); b1 = fmaxf(b1, rmx[1][i]);
            a2 = fminf(a2, rmn[2][i]); b2 = fmaxf(b2, rmx[2][i]);
        }
        float* bb = &g_bbox[ch * 6];
        bb[0] = a0; bb[1] = b0; bb[2] = a1; bb[3] = b1; bb[4] = a2; bb[5] = b2;
    }
}

// ---- Main FPS kernel: one CTA per batch ----
__global__ void __launch_bounds__(T, 1)
fps_kernel(const float* __restrict__ pts, const int* __restrict__ init_idx,
           float* __restrict__ out)
{
    __shared__ float sbox[NCH * 6];   // chunk bboxes
    __shared__ u64   scb[NCH];        // chunk best key: (dist<<32)|~origidx
    __shared__ float scx[NCH], scy[NCH], scz[NCH];  // chunk best coords
    __shared__ u32   swl[NCH];        // worklist
    __shared__ u32   swc[2];          // parity-buffered worklist counter
    __shared__ float sbc[4];          // winner broadcast (x,y,z)

    const int b    = blockIdx.x;
    const int t    = threadIdx.x;
    const int warp = t >> 5, lane = t & 31;
    const int gbase = b * N;

    const float4* __restrict__ gp = g_p + gbase;
    float*        __restrict__ gd = g_dist + gbase;

    // ---- init ----
    for (int i = t; i < NCH * 6; i += T) sbox[i] = g_bbox[b * NCH * 6 + i];
    if (t < NCH) {
        scb[t] = ((u64)__float_as_uint(1e10f)) << 32;  // forces touch at k=1
        scx[t] = 0.f; scy[t] = 0.f; scz[t] = 0.f;
    }
    if (t == 0) { swc[0] = 0; swc[1] = 0; }

    const int idx0 = init_idx[b];
    float lx = pts[3 * (gbase + idx0) + 0];
    float ly = pts[3 * (gbase + idx0) + 1];
    float lz = pts[3 * (gbase + idx0) + 2];
    if (t == 0) {
        out[(b * K + 0) * 3 + 0] = lx;
        out[(b * K + 0) * 3 + 1] = ly;
        out[(b * K + 0) * 3 + 2] = lz;
    }
    __syncthreads();

    // ---- K-1 sequential iterations ----
    for (int k = 1; k < K; k++) {
        // phase A: zero next-parity counter; bound-check all chunks
        if (t == 0) swc[(k + 1) & 1] = 0;
        if (t < NCH) {
            const float* bb = &sbox[t * 6];
            float dx = fmaxf(0.0f, fmaxf(bb[0] - lx, lx - bb[1]));
            float dy = fmaxf(0.0f, fmaxf(bb[2] - ly, ly - bb[3]));
            float dz = fmaxf(0.0f, fmaxf(bb[4] - lz, lz - bb[5]));
            float lb2 = __fmaf_rn(dx, dx, __fmaf_rn(dy, dy, dz * dz));
            float cub = __uint_as_float((u32)(scb[t] >> 32));
            if (lb2 * 0.99999f < cub) {   // conservative margin
                u32 p = atomicAdd(&swc[k & 1], 1u);
                swl[p] = (u32)t;
            }
        }
        __syncthreads();
        const int nw = (int)swc[k & 1];

        // phase B: warps update touched chunks (256 pts each)
        for (int wi = warp; wi < nw; wi += 32) {
            int c = (int)swl[wi];
            u64 bk = 0ULL;
            float bx = 0.f, by = 0.f, bz = 0.f;
            #pragma unroll
            for (int i = 0; i < 2; i++) {
                int f = c * 64 + i * 32 + lane;      // dist float4 index
                float4 D = ((float4*)gd)[f];
                float* Dv = (float*)&D;
                #pragma unroll
                for (int cc = 0; cc < 4; cc++) {
                    float4 p = gp[4 * f + cc];
                    float dx = p.x - lx, dy = p.y - ly, dz = p.z - lz;
                    float d2 = __fmaf_rn(dx, dx, __fmaf_rn(dy, dy, dz * dz));
                    float nd = fminf(Dv[cc], d2);
                    Dv[cc] = nd;
                    u64 key = (((u64)__float_as_uint(nd)) << 32) |
                              (u32)(~(u32)__float_as_int(p.w));
                    if (key > bk) { bk = key; bx = p.x; by = p.y; bz = p.z; }
                }
                ((float4*)gd)[f] = D;
            }
            // warp reduce key with coords riding along
            #pragma unroll
            for (int o = 16; o > 0; o >>= 1) {
                u64   ok = __shfl_xor_sync(0xffffffffu, bk, o);
                float ox = __shfl_xor_sync(0xffffffffu, bx, o);
                float oy = __shfl_xor_sync(0xffffffffu, by, o);
                float oz = __shfl_xor_sync(0xffffffffu, bz, o);
                if (ok > bk) { bk = ok; bx = ox; by = oy; bz = oz; }
            }
            if (lane == 0) {
                scb[c] = bk;
                scx[c] = bx; scy[c] = by; scz[c] = bz;
            }
        }
        __syncthreads();

        // phase C: warp0 reduces 512 chunk keys, publishes winner
        if (warp == 0) {
            u64 bk = 0ULL; int bc = 0;
            #pragma unroll
            for (int i = 0; i < NCH / 32; i++) {
                u64 e = scb[lane + 32 * i];
                if (e > bk) { bk = e; bc = lane + 32 * i; }
            }
            #pragma unroll
            for (int o = 16; o > 0; o >>= 1) {
                u64 ok = __shfl_xor_sync(0xffffffffu, bk, o);
                int oc = __shfl_xor_sync(0xffffffffu, bc, o);
                if (ok > bk) { bk = ok; bc = oc; }
            }
            if (lane == 0) {
                float wx = scx[bc], wy = scy[bc], wz = scz[bc];
                sbc[0] = wx; sbc[1] = wy; sbc[2] = wz;
                out[(b * K + k) * 3 + 0] = wx;
                out[(b * K + k) * 3 + 1] = wy;
                out[(b * K + k) * 3 + 2] = wz;
            }
        }
        __syncthreads();

        lx = sbc[0]; ly = sbc[1]; lz = sbc[2];
    }
}

extern "C" void kernel_launch(void* const* d_in, const int* in_sizes, int n_in,
                              void* d_out, int out_size) {
    const float* pts  = (const float*)d_in[0];
    const int*   init = (const int*)d_in[1];
    float*       out  = (float*)d_out;

    const int tot = B * N;
    zero_hist_kernel<<<(B * CELLS + 255) / 256, 256>>>();
    cell_hist_kernel<<<(tot + 255) / 256, 256>>>(pts);
    cell_scan_kernel<<<B, 1024>>>();
    scatter_kernel<<<(tot + 255) / 256, 256>>>(pts);
    chunk_bbox_kernel<<<B * NCH, 256>>>();

    fps_kernel<<<B, T>>>(pts, init, out);
}